// round 11
// baseline (speedup 1.0000x reference)
#include <cuda_runtime.h>
#include <cuda_fp16.h>
#include <cstdint>
#include <cstddef>
#include <cstring>

// TensorFusion via mma.sync fp16 2-term split — compute_103-safe.
// out1[b,h] = sum_i a_h[b,i] * (G[b,:] @ W1_i),  G[b,jk] = v_h[b,j]*t_h[b,k]
// G = Gh + Gl (fp16 hi/lo); terms Gh*Wh + Gl*Wh.
// 256-thread CTAs, 2 CTAs/SM (independent barriers overlap),
// pair-batched W staging (sync per 2 i), term-major MMA ordering.
// Grid 4 btiles x 67 jk-splits (KC=64) = 268 CTAs.

#define NSPLIT 67
#define KC 64
#define JK_TOTAL 4225
#define NI 65

__device__ float g_partial[NSPLIT * 512 * 64];
__device__ float g_h1[512 * 64];

// ---------- helpers ----------
__device__ __forceinline__ uint32_t smem_u32(const void* p) {
    uint32_t r;
    asm("{ .reg .u64 t; cvta.to.shared.u64 t, %1; cvt.u32.u64 %0, t; }" : "=r"(r) : "l"(p));
    return r;
}
__device__ __forceinline__ uint32_t h2u(half2 h) {
    uint32_t u;
    memcpy(&u, &h, 4);
    return u;
}
#define LDSM4(R, ADDR) \
    asm volatile("ldmatrix.sync.aligned.m8n8.x4.shared.b16 {%0,%1,%2,%3}, [%4];" \
                 : "=r"((R)[0]), "=r"((R)[1]), "=r"((R)[2]), "=r"((R)[3]) : "r"(ADDR))
#define LDSM4T(R, ADDR) \
    asm volatile("ldmatrix.sync.aligned.m8n8.x4.trans.shared.b16 {%0,%1,%2,%3}, [%4];" \
                 : "=r"((R)[0]), "=r"((R)[1]), "=r"((R)[2]), "=r"((R)[3]) : "r"(ADDR))
#define MMA_F16(D, A, B0, B1) \
    asm volatile("mma.sync.aligned.m16n8k16.row.col.f32.f16.f16.f32 " \
                 "{%0,%1,%2,%3}, {%4,%5,%6,%7}, {%8,%9}, {%0,%1,%2,%3};" \
                 : "+f"((D)[0]), "+f"((D)[1]), "+f"((D)[2]), "+f"((D)[3]) \
                 : "r"((A)[0]), "r"((A)[1]), "r"((A)[2]), "r"((A)[3]), "r"(B0), "r"(B1))

// ---------- smem layout ----------
// W: 2 pair-buffers, each 2 i-slots of [64 rows(k)][72 cols(h)] fp16 (stride 144B)
// G hi/lo: [128 rows(b)][72 cols(jk)] fp16
#define W_STRIDE 72
#define WI_BYTES (64 * W_STRIDE * 2)            // 9216 per i-slot
#define WP_BYTES (2 * WI_BYTES)                 // 18432 per pair-buffer
#define SM_WBUF  0                              // 2 pair-bufs -> 36864
#define G_STRIDE 72
#define SM_GHI   (2 * WP_BYTES)                 // 36864
#define SM_GLO   (SM_GHI + 128 * G_STRIDE * 2)  // 55296
#define SMEM_TOTAL (SM_GLO + 128 * G_STRIDE * 2) // 73728

__global__ __launch_bounds__(256, 2)
void fusion_mma_kernel(const float* __restrict__ l, const float* __restrict__ a,
                       const float* __restrict__ v, const float* __restrict__ W1) {
    extern __shared__ __align__(1024) char smem[];
    const uint32_t sb = smem_u32(smem);
    const int tid  = threadIdx.x;
    const int warp = tid >> 5;      // 0..7 = m-tile
    const int lane = tid & 31;
    const int b0   = blockIdx.x * 128;
    const int jk0  = blockIdx.y * KC;

    // ---- build G tile [128][64] fp16 hi/lo ----
    {
        int r  = tid >> 1;
        int c0 = (tid & 1) * 32;
        const float* lrow = l + (size_t)(b0 + r) * 64;
        const float* vrow = v + (size_t)(b0 + r) * 64;
        int jk = jk0 + c0;
        int j  = jk / 65, k = jk - j * 65;
        char* gh = smem + SM_GHI + (size_t)(r * G_STRIDE + c0) * 2;
        char* gl = smem + SM_GLO + (size_t)(r * G_STRIDE + c0) * 2;
        #pragma unroll
        for (int c = 0; c < 32; c += 2) {
            float g0 = 0.0f, g1 = 0.0f;
            if (jk < JK_TOTAL)
                g0 = (j ? __ldg(&vrow[j - 1]) : 1.0f) * (k ? __ldg(&lrow[k - 1]) : 1.0f);
            ++jk; if (++k == 65) { k = 0; ++j; }
            if (jk < JK_TOTAL)
                g1 = (j ? __ldg(&vrow[j - 1]) : 1.0f) * (k ? __ldg(&lrow[k - 1]) : 1.0f);
            ++jk; if (++k == 65) { k = 0; ++j; }
            half2 hp = __floats2half2_rn(g0, g1);
            float2 hf = __half22float2(hp);
            half2 lp = __floats2half2_rn(g0 - hf.x, g1 - hf.y);
            *(half2*)(gh + c * 2) = hp;
            *(half2*)(gl + c * 2) = lp;
        }
    }

    // ---- W staging mapping: thread t -> row t>>2 (k 0..63), cols (t&3)*16..+16 ----
    const int wr_row = tid >> 2;
    const int wr_c0  = (tid & 3) * 16;
    const bool wrow_ok = (jk0 + wr_row) < JK_TOTAL;
    const size_t w_src_base = (size_t)(jk0 + wr_row) * 64 + wr_c0;
    const size_t w_sts_off  = (size_t)(wr_row * W_STRIDE + wr_c0) * 2;

    // stage pair 0 (i=0,1) into pair-buf 0
    #pragma unroll
    for (int s = 0; s < 2; ++s) {
        float4 w0 = make_float4(0.f,0.f,0.f,0.f), w1 = w0, w2 = w0, w3 = w0;
        if (wrow_ok) {
            const float4* src = (const float4*)(W1 + (size_t)s * JK_TOTAL * 64 + w_src_base);
            w0 = __ldg(src); w1 = __ldg(src + 1); w2 = __ldg(src + 2); w3 = __ldg(src + 3);
        }
        uint4 pa, pb;
        pa.x = h2u(__floats2half2_rn(w0.x, w0.y)); pa.y = h2u(__floats2half2_rn(w0.z, w0.w));
        pa.z = h2u(__floats2half2_rn(w1.x, w1.y)); pa.w = h2u(__floats2half2_rn(w1.z, w1.w));
        pb.x = h2u(__floats2half2_rn(w2.x, w2.y)); pb.y = h2u(__floats2half2_rn(w2.z, w2.w));
        pb.z = h2u(__floats2half2_rn(w3.x, w3.y)); pb.w = h2u(__floats2half2_rn(w3.z, w3.w));
        *(uint4*)(smem + SM_WBUF + (size_t)s * WI_BYTES + w_sts_off)      = pa;
        *(uint4*)(smem + SM_WBUF + (size_t)s * WI_BYTES + w_sts_off + 16) = pb;
    }
    __syncthreads();

    // ---- preload A (G) fragments into registers (i-invariant) ----
    uint32_t AH[4][4], AL[4][4];
    {
        const uint32_t a_row = (uint32_t)(warp * 16 + (lane & 7) + ((lane >> 3) & 1) * 8);
        const uint32_t a_off = a_row * (G_STRIDE * 2) + ((lane >> 4) & 1) * 16;
        #pragma unroll
        for (int ks = 0; ks < 4; ++ks) {
            LDSM4(AH[ks], sb + SM_GHI + a_off + (uint32_t)ks * 32);
            LDSM4(AL[ks], sb + SM_GLO + a_off + (uint32_t)ks * 32);
        }
    }

    const uint32_t b_row   = (uint32_t)((lane & 7) + ((lane >> 3) & 1) * 8);
    const uint32_t b_colb16 = ((lane >> 4) & 1) * 16;   // bytes

    float acc[8][4];
    #pragma unroll
    for (int nt = 0; nt < 8; ++nt)
        #pragma unroll
        for (int q = 0; q < 4; ++q) acc[nt][q] = 0.0f;

    const int arow0 = warp * 16 + (lane >> 2);
    const float* a_r0 = a + (size_t)(b0 + arow0) * 64;
    const float* a_r1 = a + (size_t)(b0 + arow0 + 8) * 64;

    // compute-one-i macro
    #define COMPUTE_I(WB, AV0, AV1) do {                                           \
        _Pragma("unroll")                                                          \
        for (int h = 0; h < 2; ++h) {                                              \
            float d[4][4];                                                         \
            _Pragma("unroll")                                                      \
            for (int ntl = 0; ntl < 4; ++ntl)                                      \
                { d[ntl][0]=0.f; d[ntl][1]=0.f; d[ntl][2]=0.f; d[ntl][3]=0.f; }    \
            _Pragma("unroll")                                                      \
            for (int ks = 0; ks < 4; ++ks) {                                       \
                uint32_t bh[2][4];                                                 \
                uint32_t roff = ((uint32_t)ks * 16 + b_row) * (W_STRIDE * 2)       \
                                + (uint32_t)h * 64 + b_colb16;                     \
                LDSM4T(bh[0], (WB) + roff);                                        \
                LDSM4T(bh[1], (WB) + roff + 32);                                   \
                _Pragma("unroll")                                                  \
                for (int ntl = 0; ntl < 4; ++ntl) {                                \
                    const int g = ntl >> 1, o = (ntl & 1) * 2;                     \
                    MMA_F16(d[ntl], AH[ks], bh[g][o], bh[g][o + 1]);               \
                }                                                                  \
                _Pragma("unroll")                                                  \
                for (int ntl = 0; ntl < 4; ++ntl) {                                \
                    const int g = ntl >> 1, o = (ntl & 1) * 2;                     \
                    MMA_F16(d[ntl], AL[ks], bh[g][o], bh[g][o + 1]);               \
                }                                                                  \
            }                                                                      \
            _Pragma("unroll")                                                      \
            for (int ntl = 0; ntl < 4; ++ntl) {                                    \
                const int nt = h * 4 + ntl;                                        \
                acc[nt][0] = fmaf((AV0), d[ntl][0], acc[nt][0]);                   \
                acc[nt][1] = fmaf((AV0), d[ntl][1], acc[nt][1]);                   \
                acc[nt][2] = fmaf((AV1), d[ntl][2], acc[nt][2]);                   \
                acc[nt][3] = fmaf((AV1), d[ntl][3], acc[nt][3]);                   \
            }                                                                      \
        }                                                                          \
    } while (0)

    for (int p = 0; p <= 32; ++p) {
        const int i0 = 2 * p;
        const int i1 = 2 * p + 1;
        const uint32_t wpb = sb + SM_WBUF + (uint32_t)(p & 1) * WP_BYTES;

        // a_h scalars for this pair
        float av00 = (i0 == 0) ? 1.0f : __ldg(a_r0 + i0 - 1);
        float av01 = (i0 == 0) ? 1.0f : __ldg(a_r1 + i0 - 1);
        float av10 = 0.f, av11 = 0.f;
        if (i1 < NI) { av10 = __ldg(a_r0 + i1 - 1); av11 = __ldg(a_r1 + i1 - 1); }

        // LDG next pair (i=2p+2, 2p+3)
        float4 w0[2], w1[2], w2[2], w3[2];
        const bool have_next = (p < 32);
        if (have_next) {
            #pragma unroll
            for (int s = 0; s < 2; ++s) {
                int ii = 2 * p + 2 + s;
                w0[s] = make_float4(0.f,0.f,0.f,0.f); w1[s] = w0[s]; w2[s] = w0[s]; w3[s] = w0[s];
                if (ii < NI && wrow_ok) {
                    const float4* src = (const float4*)(W1 + (size_t)ii * JK_TOTAL * 64 + w_src_base);
                    w0[s] = __ldg(src); w1[s] = __ldg(src + 1);
                    w2[s] = __ldg(src + 2); w3[s] = __ldg(src + 3);
                }
            }
        }

        // compute i0
        COMPUTE_I(wpb, av00, av01);

        // STS next pair into other buffer (covered LDG latency by i0's MMAs)
        if (have_next) {
            char* dst = smem + SM_WBUF + (size_t)((p + 1) & 1) * WP_BYTES;
            #pragma unroll
            for (int s = 0; s < 2; ++s) {
                uint4 pa, pb;
                pa.x = h2u(__floats2half2_rn(w0[s].x, w0[s].y)); pa.y = h2u(__floats2half2_rn(w0[s].z, w0[s].w));
                pa.z = h2u(__floats2half2_rn(w1[s].x, w1[s].y)); pa.w = h2u(__floats2half2_rn(w1[s].z, w1[s].w));
                pb.x = h2u(__floats2half2_rn(w2[s].x, w2[s].y)); pb.y = h2u(__floats2half2_rn(w2[s].z, w2[s].w));
                pb.z = h2u(__floats2half2_rn(w3[s].x, w3[s].y)); pb.w = h2u(__floats2half2_rn(w3[s].z, w3[s].w));
                *(uint4*)(dst + (size_t)s * WI_BYTES + w_sts_off)      = pa;
                *(uint4*)(dst + (size_t)s * WI_BYTES + w_sts_off + 16) = pb;
            }
        }

        // compute i1
        if (i1 < NI) {
            COMPUTE_I(wpb + WI_BYTES, av10, av11);
        }
        __syncthreads();
    }
    #undef COMPUTE_I

    // ---- write split partial ----
    {
        float* gp = g_partial + (size_t)blockIdx.y * (512 * 64) + (size_t)b0 * 64;
        const int c0 = (lane & 3) * 2;
        #pragma unroll
        for (int nt = 0; nt < 8; ++nt) {
            *(float2*)(gp + (size_t)arow0 * 64 + nt * 8 + c0)       = make_float2(acc[nt][0], acc[nt][1]);
            *(float2*)(gp + (size_t)(arow0 + 8) * 64 + nt * 8 + c0) = make_float2(acc[nt][2], acc[nt][3]);
        }
    }
}

// ---------- reduce: sum 67 partials + b1 + tanh -> g_h1 ----------
__global__ __launch_bounds__(256, 1)
void reduce_kernel(const float* __restrict__ b1) {
    int idx = blockIdx.x * 256 + threadIdx.x;    // 0..32767
    float s0 = 0.f, s1 = 0.f;
    #pragma unroll
    for (int r = 0; r + 1 < NSPLIT; r += 2) {
        s0 += g_partial[(size_t)r * 32768 + idx];
        s1 += g_partial[(size_t)(r + 1) * 32768 + idx];
    }
    s0 += g_partial[(size_t)(NSPLIT - 1) * 32768 + idx];
    g_h1[idx] = tanhf(s0 + s1 + b1[idx & 63]);
}

// ---------- MLP layers 2,3 ----------
__global__ __launch_bounds__(256, 1)
void mlp_kernel(const float* __restrict__ W2, const float* __restrict__ b2,
                const float* __restrict__ W3, const float* __restrict__ b3,
                float* __restrict__ out) {
    __shared__ __align__(16) float h_s[64 * 65];
    __shared__ __align__(16) float w_s[64 * 64];
    const int tid = threadIdx.x;
    const int bt  = blockIdx.x;      // 0..7

    for (int x = tid; x < 4096; x += 256)
        h_s[(x >> 6) * 65 + (x & 63)] = g_h1[bt * 4096 + x];
    for (int x = tid; x < 1024; x += 256)
        ((float4*)w_s)[x] = ((const float4*)W2)[x];
    __syncthreads();

    const int hg = tid & 7, bg = tid >> 3;
    const int h0 = hg * 8;
    float acc[2][8];

    #pragma unroll
    for (int bb = 0; bb < 2; ++bb)
        #pragma unroll
        for (int hh = 0; hh < 8; ++hh) acc[bb][hh] = 0.0f;
    #pragma unroll 4
    for (int k = 0; k < 64; ++k) {
        float hv0 = h_s[(bg * 2 + 0) * 65 + k];
        float hv1 = h_s[(bg * 2 + 1) * 65 + k];
        const float* wr = &w_s[k * 64 + h0];
        #pragma unroll
        for (int hh = 0; hh < 8; ++hh) {
            float wv = wr[hh];
            acc[0][hh] += hv0 * wv;
            acc[1][hh] += hv1 * wv;
        }
    }
    __syncthreads();
    #pragma unroll
    for (int bb = 0; bb < 2; ++bb)
        #pragma unroll
        for (int hh = 0; hh < 8; ++hh)
            h_s[(bg * 2 + bb) * 65 + h0 + hh] = tanhf(acc[bb][hh] + b2[h0 + hh]);
    for (int x = tid; x < 1024; x += 256)
        ((float4*)w_s)[x] = ((const float4*)W3)[x];
    __syncthreads();

    #pragma unroll
    for (int bb = 0; bb < 2; ++bb)
        #pragma unroll
        for (int hh = 0; hh < 8; ++hh) acc[bb][hh] = 0.0f;
    #pragma unroll 4
    for (int k = 0; k < 64; ++k) {
        float hv0 = h_s[(bg * 2 + 0) * 65 + k];
        float hv1 = h_s[(bg * 2 + 1) * 65 + k];
        const float* wr = &w_s[k * 64 + h0];
        #pragma unroll
        for (int hh = 0; hh < 8; ++hh) {
            float wv = wr[hh];
            acc[0][hh] += hv0 * wv;
            acc[1][hh] += hv1 * wv;
        }
    }
    #pragma unroll
    for (int bb = 0; bb < 2; ++bb) {
        int b = bt * 64 + bg * 2 + bb;
        float o[8];
        #pragma unroll
        for (int hh = 0; hh < 8; ++hh)
            o[hh] = tanhf(acc[bb][hh] + b3[h0 + hh]);
        *(float4*)(&out[b * 64 + h0])     = make_float4(o[0], o[1], o[2], o[3]);
        *(float4*)(&out[b * 64 + h0 + 4]) = make_float4(o[4], o[5], o[6], o[7]);
    }
}

extern "C" void kernel_launch(void* const* d_in, const int* in_sizes, int n_in,
                              void* d_out, int out_size) {
    (void)in_sizes; (void)n_in; (void)out_size;
    const float* l  = (const float*)d_in[0];
    const float* a  = (const float*)d_in[1];
    const float* v  = (const float*)d_in[2];
    const float* W1 = (const float*)d_in[3];
    const float* b1 = (const float*)d_in[4];
    const float* W2 = (const float*)d_in[5];
    const float* b2 = (const float*)d_in[6];
    const float* W3 = (const float*)d_in[7];
    const float* b3 = (const float*)d_in[8];
    float* out = (float*)d_out;

    cudaFuncSetAttribute(fusion_mma_kernel,
                         cudaFuncAttributeMaxDynamicSharedMemorySize, SMEM_TOTAL);
    dim3 grid1(4, NSPLIT);
    fusion_mma_kernel<<<grid1, 256, SMEM_TOTAL>>>(l, a, v, W1);
    reduce_kernel<<<128, 256>>>(b1);
    mlp_kernel<<<8, 256>>>(W2, b2, W3, b3, out);
}